// round 13
// baseline (speedup 1.0000x reference)
#include <cuda_runtime.h>
#include <cuda_fp16.h>
#include <math.h>

#define BB 4
#define NN 512
#define DD 256

// ---------------- scratch (static device globals: allocation-free) ----------
__device__ __align__(16) __half g_q[BB * NN * DD];     // 1 MB
__device__ __align__(16) __half g_k[BB * NN * DD];     // 1 MB
__device__ __align__(16) float  g_wei[BB * NN * NN];   // 4 MB (raw scores)
__device__ __align__(16) __half g_weih[BB * NN * NN];  // 2 MB (softmaxed, fp16)
__device__ __align__(16) __half g_xh[BB * NN * DD];    // 1 MB (X in fp16)
__device__ __align__(16) __half g_wh[DD * DD];         // Wa_w fp16
__device__ __align__(16) __half g_uh[DD * DD];         // Ua_w fp16

// ---------------- small PTX helpers ------------------------------------------
__device__ __forceinline__ unsigned tanh_h2(unsigned xi) {
    unsigned yi;
    asm("tanh.approx.f16x2 %0, %1;" : "=r"(yi) : "r"(xi));
    return yi;
}
__device__ __forceinline__ unsigned hadd2_u(unsigned a, unsigned b) {
    unsigned c;
    asm("add.f16x2 %0, %1, %2;" : "=r"(c) : "r"(a), "r"(b));
    return c;
}
__device__ __forceinline__ unsigned hfma2_u(unsigned a, unsigned b, unsigned c) {
    unsigned d;
    asm("fma.rn.f16x2 %0, %1, %2, %3;" : "=r"(d) : "r"(a), "r"(b), "r"(c));
    return d;
}
__device__ __forceinline__ unsigned smem_u32(const void* p) {
    return (unsigned)__cvta_generic_to_shared(p);
}
__device__ __forceinline__ void cp16(void* dst, const void* src) {
    asm volatile("cp.async.cg.shared.global [%0], [%1], 16;"
        :: "r"(smem_u32(dst)), "l"(src));
}
#define CP_COMMIT() asm volatile("cp.async.commit_group;")
#define CP_WAIT0()  asm volatile("cp.async.wait_group 0;")

__device__ __forceinline__ void ldsm_x4(unsigned* r, const __half* p) {
    unsigned a = smem_u32(p);
    asm volatile("ldmatrix.sync.aligned.m8n8.x4.shared.b16 {%0,%1,%2,%3}, [%4];"
        : "=r"(r[0]), "=r"(r[1]), "=r"(r[2]), "=r"(r[3]) : "r"(a));
}
__device__ __forceinline__ void ldsm_x4_trans(unsigned* r, const __half* p) {
    unsigned a = smem_u32(p);
    asm volatile("ldmatrix.sync.aligned.m8n8.x4.trans.shared.b16 {%0,%1,%2,%3}, [%4];"
        : "=r"(r[0]), "=r"(r[1]), "=r"(r[2]), "=r"(r[3]) : "r"(a));
}
__device__ __forceinline__ void mma16816(float* c, const unsigned* a,
                                         unsigned b0, unsigned b1) {
    asm volatile("mma.sync.aligned.m16n8k16.row.col.f32.f16.f16.f32 "
        "{%0,%1,%2,%3}, {%4,%5,%6,%7}, {%8,%9}, {%0,%1,%2,%3};"
        : "+f"(c[0]), "+f"(c[1]), "+f"(c[2]), "+f"(c[3])
        : "r"(a[0]), "r"(a[1]), "r"(a[2]), "r"(a[3]), "r"(b0), "r"(b1));
}

// ---------------- kernel 0: fp32 -> fp16 conversions --------------------------
// float4 units: X = 131072 f4; Wa_w = 16384 (cum 147456); Ua_w = 16384 (cum 163840)
__global__ __launch_bounds__(256) void conv_kernel(
    const float4* __restrict__ X4, const float4* __restrict__ Wa4,
    const float4* __restrict__ Ua4)
{
    int i = blockIdx.x * 256 + threadIdx.x;     // 0 .. 163839
    const float4* src;
    uint2* dst;
    int j;
    if (i < 131072)      { src = X4;  j = i;          dst = (uint2*)g_xh; }
    else if (i < 147456) { src = Wa4; j = i - 131072; dst = (uint2*)g_wh; }
    else                 { src = Ua4; j = i - 147456; dst = (uint2*)g_uh; }
    float4 v = src[j];
    __half2 h01 = __floats2half2_rn(v.x, v.y);
    __half2 h23 = __floats2half2_rn(v.z, v.w);
    uint2 o;
    o.x = *reinterpret_cast<unsigned*>(&h01);
    o.y = *reinterpret_cast<unsigned*>(&h23);
    dst[j] = o;
}

// ---------------- kernel 1: q/k projections via HMMA, cp.async pipelined -----
__global__ __launch_bounds__(256) void proj_mma(
    const float* __restrict__ Wb, const float* __restrict__ Ub)
{
    __shared__ __half As[2][128][40];
    __shared__ __half Bs[2][64][40];

    const __half* A    = g_xh;
    const __half* Bw   = blockIdx.z ? g_uh : g_wh;
    const float*  bias = blockIdx.z ? Ub : Wb;
    __half*       out  = blockIdx.z ? g_k : g_q;

    const int bn = blockIdx.x * 64;
    const int bm = blockIdx.y * 128;
    const int tid = threadIdx.x, warp = tid >> 5, lane = tid & 31;
    const int wm = warp >> 1, wn = warp & 1;
    const int gq = lane >> 2, tq = lane & 3;

    const int ar0 = tid >> 2, aq = tid & 3;
    const int br  = tid >> 2, bq = tid & 3;

    float acc[2][4][4] = {};

    cp16(&As[0][ar0][aq * 8],      &A[(bm + ar0) * DD + aq * 8]);
    cp16(&As[0][ar0 + 64][aq * 8], &A[(bm + ar0 + 64) * DD + aq * 8]);
    cp16(&Bs[0][br][bq * 8],       &Bw[(bn + br) * DD + bq * 8]);
    CP_COMMIT();

    #pragma unroll
    for (int it = 0; it < 8; it++) {
        CP_WAIT0();
        __syncthreads();
        if (it < 7) {
            int nk = (it + 1) * 32, s = (it + 1) & 1;
            cp16(&As[s][ar0][aq * 8],      &A[(bm + ar0) * DD + nk + aq * 8]);
            cp16(&As[s][ar0 + 64][aq * 8], &A[(bm + ar0 + 64) * DD + nk + aq * 8]);
            cp16(&Bs[s][br][bq * 8],       &Bw[(bn + br) * DD + nk + bq * 8]);
            CP_COMMIT();
        }
        const int cur = it & 1;

        #pragma unroll
        for (int ks = 0; ks < 2; ks++) {
            int kc = ks * 16;
            unsigned a[2][4], bf[2][4];
            #pragma unroll
            for (int tm = 0; tm < 2; tm++) {
                int r = wm * 32 + tm * 16 + (lane & 15);
                int c = kc + 8 * (lane >> 4);
                ldsm_x4(a[tm], &As[cur][r][c]);
            }
            #pragma unroll
            for (int tn = 0; tn < 2; tn++) {
                int r = wn * 32 + tn * 16 + (lane & 7) + 8 * (lane >> 4);
                int c = kc + 8 * ((lane >> 3) & 1);
                ldsm_x4(bf[tn], &Bs[cur][r][c]);
            }
            #pragma unroll
            for (int tm = 0; tm < 2; tm++)
                #pragma unroll
                for (int tn8 = 0; tn8 < 4; tn8++)
                    mma16816(acc[tm][tn8], a[tm],
                             bf[tn8 >> 1][(tn8 & 1) * 2],
                             bf[tn8 >> 1][(tn8 & 1) * 2 + 1]);
        }
    }

    #pragma unroll
    for (int tm = 0; tm < 2; tm++) {
        #pragma unroll
        for (int tn8 = 0; tn8 < 4; tn8++) {
            int c = bn + wn * 32 + tn8 * 8 + 2 * tq;
            float2 bv = *(const float2*)&bias[c];
            int r0 = bm + wm * 32 + tm * 16 + gq;
            __half2 h0 = __floats2half2_rn(acc[tm][tn8][0] + bv.x,
                                           acc[tm][tn8][1] + bv.y);
            __half2 h1 = __floats2half2_rn(acc[tm][tn8][2] + bv.x,
                                           acc[tm][tn8][3] + bv.y);
            *(__half2*)&out[r0 * DD + c] = h0;
            *(__half2*)&out[(r0 + 8) * DD + c] = h1;
        }
    }
}

// ---------------- kernel 2: additive-attention scores -------------------------
// wei[b,q,k] = sum_d Va[d] * tanh(q[b,q,d] + k[b,k,d])
// Dual-path tanh: d-offsets 0..19 per 32-group -> MUFU f16x2 tanh (fp16 acc);
// d-offsets 20..31 -> shared-memory piecewise-linear table on the FMA/LSU
// pipes (fp32 acc). Table: 80 segs on [0,5], y = fmaf(S_i, |x|, c_i).
// Index = round(16|x|) via magic 2^23 (bits = 0x4B000000 + n, n in [0,79]);
// round-vs-floor is safe because the PL approximant is continuous.
#define KT 32
#define QB 64
#define QSTAGE 32

__global__ __launch_bounds__(256, 2) void score_kernel(const float* __restrict__ Va)
{
    // q staging: per (row, dg): 112B = 10 half2 @0..39 | pad | 12 f32 @48..95.
    // dg offsets mod 128 = {0,112,96,80,64,48,32,16} -> conflict-free.
    __shared__ __align__(16) char q_raw[QSTAGE * 896];
    __shared__ float2 tanh_tbl[80];

    const int tid  = threadIdx.x;
    const int w    = tid >> 5;
    const int lane = tid & 31;
    const int dg   = lane >> 2;
    const int kis  = lane & 3;

    const int b     = blockIdx.z;
    const int k0    = blockIdx.x * KT;
    const int qbase = blockIdx.y * QB;
    const int krow  = k0 + w * 4 + kis;

    // build tanh table (once per block, before first __syncthreads)
    if (tid < 80) {
        float x0 = tid * 0.0625f;
        float v0 = tanhf(x0);
        float v1 = tanhf(x0 + 0.0625f);
        float S  = (v1 - v0) * 16.0f;
        tanh_tbl[tid] = make_float2(fmaf(-S, x0, v0), S);
    }

    // k row: first 10 half2 stay fp16; last 6 half2 -> 12 fp32
    unsigned kreg[10];
    float kf[12];
    {
        const uint4* kp = reinterpret_cast<const uint4*>(
            g_k + ((b * NN + krow) << 8) + dg * 32);
        uint4 t0 = kp[0], t1 = kp[1], t2 = kp[2], t3 = kp[3];
        kreg[0] = t0.x; kreg[1] = t0.y; kreg[2] = t0.z; kreg[3] = t0.w;
        kreg[4] = t1.x; kreg[5] = t1.y; kreg[6] = t1.z; kreg[7] = t1.w;
        kreg[8] = t2.x; kreg[9] = t2.y;
        float2 fa = __half22float2(*reinterpret_cast<__half2*>(&t2.z));
        float2 fb = __half22float2(*reinterpret_cast<__half2*>(&t2.w));
        float2 fc = __half22float2(*reinterpret_cast<__half2*>(&t3.x));
        float2 fd = __half22float2(*reinterpret_cast<__half2*>(&t3.y));
        float2 fe = __half22float2(*reinterpret_cast<__half2*>(&t3.z));
        float2 ff = __half22float2(*reinterpret_cast<__half2*>(&t3.w));
        kf[0]=fa.x; kf[1]=fa.y; kf[2]=fb.x; kf[3]=fb.y;
        kf[4]=fc.x; kf[5]=fc.y; kf[6]=fd.x; kf[7]=fd.y;
        kf[8]=fe.x; kf[9]=fe.y; kf[10]=ff.x; kf[11]=ff.y;
    }
    // Va: d 0..19 packed half2 (MUFU path); d 20..31 fp32 (table path)
    unsigned vh[10];
    float vf[12];
    {
        const float4* vp = reinterpret_cast<const float4*>(Va + dg * 32);
        float4 w0 = vp[0], w1 = vp[1], w2 = vp[2], w3 = vp[3], w4 = vp[4];
        __half2 p;
        p = __floats2half2_rn(w0.x, w0.y); vh[0] = *reinterpret_cast<unsigned*>(&p);
        p = __floats2half2_rn(w0.z, w0.w); vh[1] = *reinterpret_cast<unsigned*>(&p);
        p = __floats2half2_rn(w1.x, w1.y); vh[2] = *reinterpret_cast<unsigned*>(&p);
        p = __floats2half2_rn(w1.z, w1.w); vh[3] = *reinterpret_cast<unsigned*>(&p);
        p = __floats2half2_rn(w2.x, w2.y); vh[4] = *reinterpret_cast<unsigned*>(&p);
        p = __floats2half2_rn(w2.z, w2.w); vh[5] = *reinterpret_cast<unsigned*>(&p);
        p = __floats2half2_rn(w3.x, w3.y); vh[6] = *reinterpret_cast<unsigned*>(&p);
        p = __floats2half2_rn(w3.z, w3.w); vh[7] = *reinterpret_cast<unsigned*>(&p);
        p = __floats2half2_rn(w4.x, w4.y); vh[8] = *reinterpret_cast<unsigned*>(&p);
        p = __floats2half2_rn(w4.z, w4.w); vh[9] = *reinterpret_cast<unsigned*>(&p);
        float4 w5 = vp[5], w6 = vp[6], w7 = vp[7];
        vf[0]=w5.x; vf[1]=w5.y; vf[2]=w5.z; vf[3]=w5.w;
        vf[4]=w6.x; vf[5]=w6.y; vf[6]=w6.z; vf[7]=w6.w;
        vf[8]=w7.x; vf[9]=w7.y; vf[10]=w7.z; vf[11]=w7.w;
    }

    const int srow = tid >> 3, sdg = tid & 7;   // staging coords

    for (int qc = 0; qc < QB; qc += QSTAGE) {
        __syncthreads();
        // stage 32 rows: mixed layout (10 half2 + 12 f32 per 32-d group)
        {
            const uint4* src = reinterpret_cast<const uint4*>(
                g_q + ((b * NN + qbase + qc + srow) << 8) + sdg * 32);
            uint4 s0 = src[0], s1 = src[1], s2 = src[2], s3 = src[3];
            char* dst = q_raw + srow * 896 + sdg * 112;
            *(uint4*)(dst)      = s0;
            *(uint4*)(dst + 16) = s1;
            *(uint2*)(dst + 32) = make_uint2(s2.x, s2.y);
            float2 fa = __half22float2(*reinterpret_cast<__half2*>(&s2.z));
            float2 fb = __half22float2(*reinterpret_cast<__half2*>(&s2.w));
            float2 fc = __half22float2(*reinterpret_cast<__half2*>(&s3.x));
            float2 fd = __half22float2(*reinterpret_cast<__half2*>(&s3.y));
            float2 fe = __half22float2(*reinterpret_cast<__half2*>(&s3.z));
            float2 ff = __half22float2(*reinterpret_cast<__half2*>(&s3.w));
            *(float4*)(dst + 48) = make_float4(fa.x, fa.y, fb.x, fb.y);
            *(float4*)(dst + 64) = make_float4(fc.x, fc.y, fd.x, fd.y);
            *(float4*)(dst + 80) = make_float4(fe.x, fe.y, ff.x, ff.y);
        }
        __syncthreads();

        const char* qp = q_raw + dg * 112;
        #pragma unroll 2
        for (int qi = 0; qi < QSTAGE; qi++, qp += 896) {
            uint4 qa = *(const uint4*)(qp);
            uint4 qb = *(const uint4*)(qp + 16);
            uint2 qcv = *(const uint2*)(qp + 32);
            float4 f0 = *(const float4*)(qp + 48);
            float4 f1 = *(const float4*)(qp + 64);
            float4 f2 = *(const float4*)(qp + 80);

            // MUFU path: 10 half2
            unsigned h0 = 0u, h1 = 0u, h2 = 0u, h3 = 0u, t;
            t = tanh_h2(hadd2_u(qa.x,  kreg[0])); h0 = hfma2_u(t, vh[0], h0);
            t = tanh_h2(hadd2_u(qa.y,  kreg[1])); h1 = hfma2_u(t, vh[1], h1);
            t = tanh_h2(hadd2_u(qa.z,  kreg[2])); h2 = hfma2_u(t, vh[2], h2);
            t = tanh_h2(hadd2_u(qa.w,  kreg[3])); h3 = hfma2_u(t, vh[3], h3);
            t = tanh_h2(hadd2_u(qb.x,  kreg[4])); h0 = hfma2_u(t, vh[4], h0);
            t = tanh_h2(hadd2_u(qb.y,  kreg[5])); h1 = hfma2_u(t, vh[5], h1);
            t = tanh_h2(hadd2_u(qb.z,  kreg[6])); h2 = hfma2_u(t, vh[6], h2);
            t = tanh_h2(hadd2_u(qb.w,  kreg[7])); h3 = hfma2_u(t, vh[7], h3);
            t = tanh_h2(hadd2_u(qcv.x, kreg[8])); h0 = hfma2_u(t, vh[8], h0);
            t = tanh_h2(hadd2_u(qcv.y, kreg[9])); h1 = hfma2_u(t, vh[9], h1);

            // table path: 12 fp32 elements
            float fac0 = 0.f, fac1 = 0.f;
            const float qf[12] = {f0.x, f0.y, f0.z, f0.w,
                                  f1.x, f1.y, f1.z, f1.w,
                                  f2.x, f2.y, f2.z, f2.w};
            #pragma unroll
            for (int e = 0; e < 12; e++) {
                float x  = qf[e] + kf[e];
                float xa = fminf(fabsf(x), 4.9f);
                // n = round(16*xa) in [0,79]; bits(2^23 + n) = 0x4B000000 + n
                float m  = fmaf(xa, 16.0f, 8388608.0f);
                unsigned ib = __float_as_uint(m) & 0x7Fu;
                float2 cs = tanh_tbl[ib];
                float r = fmaf(cs.y, xa, cs.x);
                r = __uint_as_float(__float_as_uint(r) |
                                    (__float_as_uint(x) & 0x80000000u));
                if (e & 1) fac1 = fmaf(vf[e], r, fac1);
                else       fac0 = fmaf(vf[e], r, fac0);
            }

            float2 g0 = __half22float2(*reinterpret_cast<__half2*>(&h0));
            float2 g1 = __half22float2(*reinterpret_cast<__half2*>(&h1));
            float2 g2 = __half22float2(*reinterpret_cast<__half2*>(&h2));
            float2 g3 = __half22float2(*reinterpret_cast<__half2*>(&h3));
            float partial = ((g0.x + g0.y) + (g1.x + g1.y))
                          + ((g2.x + g2.y) + (g3.x + g3.y))
                          + (fac0 + fac1);
            partial += __shfl_xor_sync(0xffffffffu, partial, 16);
            partial += __shfl_xor_sync(0xffffffffu, partial, 8);
            partial += __shfl_xor_sync(0xffffffffu, partial, 4);
            if (dg == 0) {
                g_wei[((b * NN + qbase + qc + qi) << 9) + krow] = partial;
            }
        }
    }
}

// ---------------- kernel 3: masked softmax -> fp16 weights -------------------
__global__ __launch_bounds__(128) void softmax_kernel(const int* __restrict__ mask)
{
    const int row = blockIdx.x;
    const float* wrow = g_wei + row * NN;
    const int* mrow = mask + row * NN;
    const int t = threadIdx.x;
    __shared__ float red[4];

    float4 v = reinterpret_cast<const float4*>(wrow)[t];
    int4   m = reinterpret_cast<const int4*>(mrow)[t];
    if (m.x == 0) v.x = -1e30f;
    if (m.y == 0) v.y = -1e30f;
    if (m.z == 0) v.z = -1e30f;
    if (m.w == 0) v.w = -1e30f;

    float mx = fmaxf(fmaxf(v.x, v.y), fmaxf(v.z, v.w));
    #pragma unroll
    for (int s = 16; s > 0; s >>= 1) mx = fmaxf(mx, __shfl_xor_sync(0xffffffffu, mx, s));
    if ((t & 31) == 0) red[t >> 5] = mx;
    __syncthreads();
    mx = fmaxf(fmaxf(red[0], red[1]), fmaxf(red[2], red[3]));
    __syncthreads();

    v.x = __expf(v.x - mx); v.y = __expf(v.y - mx);
    v.z = __expf(v.z - mx); v.w = __expf(v.w - mx);
    float sum = (v.x + v.y) + (v.z + v.w);
    #pragma unroll
    for (int s = 16; s > 0; s >>= 1) sum += __shfl_xor_sync(0xffffffffu, sum, s);
    if ((t & 31) == 0) red[t >> 5] = sum;
    __syncthreads();
    sum = (red[0] + red[1]) + (red[2] + red[3]);
    float inv = 1.0f / sum;

    __half2 h01 = __floats2half2_rn(v.x * inv, v.y * inv);
    __half2 h23 = __floats2half2_rn(v.z * inv, v.w * inv);
    uint2 o;
    o.x = *reinterpret_cast<unsigned*>(&h01);
    o.y = *reinterpret_cast<unsigned*>(&h23);
    reinterpret_cast<uint2*>(g_weih + row * NN)[t] = o;
}

// ---------------- kernel 4: out = wei @ X via HMMA, cp.async pipelined -------
__global__ __launch_bounds__(256) void av_mma(float* __restrict__ out)
{
    __shared__ __half As[2][64][40];
    __shared__ __half Bs[2][32][72];

    const int b  = blockIdx.z;
    const int bn = blockIdx.x * 64;
    const int bm = blockIdx.y * 64;
    const __half* A  = g_weih + b * NN * NN;
    const __half* Bx = g_xh + b * NN * DD;

    const int tid = threadIdx.x, warp = tid >> 5, lane = tid & 31;
    const int wm = warp >> 2, wn = warp & 3;
    const int gq = lane >> 2, tq = lane & 3;

    const int ar = tid >> 2, aq = tid & 3;
    const int br = tid >> 3, bq = tid & 7;

    float acc[2][2][4] = {};

    cp16(&As[0][ar][aq * 8], &A[(bm + ar) * NN + aq * 8]);
    cp16(&Bs[0][br][bq * 8], &Bx[br * DD + bn + bq * 8]);
    CP_COMMIT();

    #pragma unroll 1
    for (int it = 0; it < 16; it++) {
        CP_WAIT0();
        __syncthreads();
        if (it < 15) {
            int nk = (it + 1) * 32, s = (it + 1) & 1;
            cp16(&As[s][ar][aq * 8], &A[(bm + ar) * NN + nk + aq * 8]);
            cp16(&Bs[s][br][bq * 8], &Bx[(nk + br) * DD + bn + bq * 8]);
            CP_COMMIT();
        }
        const int cur = it & 1;

        #pragma unroll
        for (int ks = 0; ks < 2; ks++) {
            int kc = ks * 16;
            unsigned a[2][4], bf[4];
            #pragma unroll
            for (int tm = 0; tm < 2; tm++) {
                int r = wm * 32 + tm * 16 + (lane & 15);
                int c = kc + 8 * (lane >> 4);
                ldsm_x4(a[tm], &As[cur][r][c]);
            }
            {
                int kr = kc + (lane & 7) + 8 * ((lane >> 3) & 1);
                int nc = wn * 16 + 8 * (lane >> 4);
                ldsm_x4_trans(bf, &Bs[cur][kr][nc]);
            }
            #pragma unroll
            for (int tm = 0; tm < 2; tm++)
                #pragma unroll
                for (int tn8 = 0; tn8 < 2; tn8++)
                    mma16816(acc[tm][tn8], a[tm], bf[tn8 * 2], bf[tn8 * 2 + 1]);
        }
    }

    #pragma unroll
    for (int tm = 0; tm < 2; tm++) {
        #pragma unroll
        for (int tn8 = 0; tn8 < 2; tn8++) {
            int c  = bn + wn * 16 + tn8 * 8 + 2 * tq;
            int r0 = bm + wm * 32 + tm * 16 + gq;
            *(float2*)&out[(b * NN + r0) * DD + c] =
                make_float2(acc[tm][tn8][0], acc[tm][tn8][1]);
            *(float2*)&out[(b * NN + r0 + 8) * DD + c] =
                make_float2(acc[tm][tn8][2], acc[tm][tn8][3]);
        }
    }
}

// ---------------- launcher ---------------------------------------------------
extern "C" void kernel_launch(void* const* d_in, const int* in_sizes, int n_in,
                              void* d_out, int out_size)
{
    const float* X    = (const float*)d_in[0];  // [4,512,256]
    const int*   mask = (const int*)  d_in[1];  // [4,512,512]
    const float* Wa_w = (const float*)d_in[2];  // [256,256]
    const float* Wa_b = (const float*)d_in[3];  // [256]
    const float* Ua_w = (const float*)d_in[4];  // [256,256]
    const float* Ua_b = (const float*)d_in[5];  // [256]
    const float* Va_w = (const float*)d_in[6];  // [1,256]
    // d_in[7] = Va_b : softmax-invariant constant -> unused

    (void)in_sizes; (void)n_in; (void)out_size;

    conv_kernel<<<640, 256>>>((const float4*)X, (const float4*)Wa_w,
                              (const float4*)Ua_w);

    dim3 pgrid(DD / 64, (BB * NN) / 128, 2);    // 128 blocks
    proj_mma<<<pgrid, 256>>>(Wa_b, Ua_b);

    dim3 sgrid(NN / KT, NN / QB, BB);           // 512 blocks
    score_kernel<<<sgrid, 256>>>(Va_w);

    softmax_kernel<<<BB * NN, 128>>>(mask);

    dim3 agrid(DD / 64, NN / 64, BB);           // 128 blocks
    av_mma<<<agrid, 256>>>((float*)d_out);
}

// round 14
// speedup vs baseline: 1.1113x; 1.1113x over previous
#include <cuda_runtime.h>
#include <cuda_fp16.h>

#define BB 4
#define NN 512
#define DD 256

// ---------------- scratch (static device globals: allocation-free) ----------
__device__ __align__(16) __half g_q[BB * NN * DD];     // 1 MB
__device__ __align__(16) __half g_k[BB * NN * DD];     // 1 MB
__device__ __align__(16) float  g_wei[BB * NN * NN];   // 4 MB (raw scores)
__device__ __align__(16) __half g_weih[BB * NN * NN];  // 2 MB (softmaxed, fp16)
__device__ __align__(16) __half g_xh[BB * NN * DD];    // 1 MB (X in fp16)
__device__ __align__(16) __half g_wh[DD * DD];         // Wa_w fp16
__device__ __align__(16) __half g_uh[DD * DD];         // Ua_w fp16

// ---------------- small PTX helpers ------------------------------------------
__device__ __forceinline__ unsigned tanh_h2(unsigned xi) {
    unsigned yi;
    asm("tanh.approx.f16x2 %0, %1;" : "=r"(yi) : "r"(xi));
    return yi;
}
__device__ __forceinline__ unsigned hadd2_u(unsigned a, unsigned b) {
    unsigned c;
    asm("add.f16x2 %0, %1, %2;" : "=r"(c) : "r"(a), "r"(b));
    return c;
}
__device__ __forceinline__ unsigned hfma2_u(unsigned a, unsigned b, unsigned c) {
    unsigned d;
    asm("fma.rn.f16x2 %0, %1, %2, %3;" : "=r"(d) : "r"(a), "r"(b), "r"(c));
    return d;
}
__device__ __forceinline__ unsigned smem_u32(const void* p) {
    return (unsigned)__cvta_generic_to_shared(p);
}
__device__ __forceinline__ void cp16(void* dst, const void* src) {
    asm volatile("cp.async.cg.shared.global [%0], [%1], 16;"
        :: "r"(smem_u32(dst)), "l"(src));
}
#define CP_COMMIT() asm volatile("cp.async.commit_group;")
#define CP_WAIT0()  asm volatile("cp.async.wait_group 0;")

__device__ __forceinline__ void ldsm_x4(unsigned* r, const __half* p) {
    unsigned a = smem_u32(p);
    asm volatile("ldmatrix.sync.aligned.m8n8.x4.shared.b16 {%0,%1,%2,%3}, [%4];"
        : "=r"(r[0]), "=r"(r[1]), "=r"(r[2]), "=r"(r[3]) : "r"(a));
}
__device__ __forceinline__ void ldsm_x4_trans(unsigned* r, const __half* p) {
    unsigned a = smem_u32(p);
    asm volatile("ldmatrix.sync.aligned.m8n8.x4.trans.shared.b16 {%0,%1,%2,%3}, [%4];"
        : "=r"(r[0]), "=r"(r[1]), "=r"(r[2]), "=r"(r[3]) : "r"(a));
}
__device__ __forceinline__ void mma16816(float* c, const unsigned* a,
                                         unsigned b0, unsigned b1) {
    asm volatile("mma.sync.aligned.m16n8k16.row.col.f32.f16.f16.f32 "
        "{%0,%1,%2,%3}, {%4,%5,%6,%7}, {%8,%9}, {%0,%1,%2,%3};"
        : "+f"(c[0]), "+f"(c[1]), "+f"(c[2]), "+f"(c[3])
        : "r"(a[0]), "r"(a[1]), "r"(a[2]), "r"(a[3]), "r"(b0), "r"(b1));
}

// ---------------- kernel 0: fp32 -> fp16 conversions --------------------------
// float4 units: X = 131072 f4; Wa_w = 16384 (cum 147456); Ua_w = 16384 (cum 163840)
__global__ __launch_bounds__(256) void conv_kernel(
    const float4* __restrict__ X4, const float4* __restrict__ Wa4,
    const float4* __restrict__ Ua4)
{
    int i = blockIdx.x * 256 + threadIdx.x;     // 0 .. 163839
    const float4* src;
    uint2* dst;
    int j;
    if (i < 131072)      { src = X4;  j = i;          dst = (uint2*)g_xh; }
    else if (i < 147456) { src = Wa4; j = i - 131072; dst = (uint2*)g_wh; }
    else                 { src = Ua4; j = i - 147456; dst = (uint2*)g_uh; }
    float4 v = src[j];
    __half2 h01 = __floats2half2_rn(v.x, v.y);
    __half2 h23 = __floats2half2_rn(v.z, v.w);
    uint2 o;
    o.x = *reinterpret_cast<unsigned*>(&h01);
    o.y = *reinterpret_cast<unsigned*>(&h23);
    dst[j] = o;
}

// ---------------- kernel 1: q/k projections via HMMA, cp.async pipelined -----
__global__ __launch_bounds__(256) void proj_mma(
    const float* __restrict__ Wb, const float* __restrict__ Ub)
{
    __shared__ __half As[2][128][40];
    __shared__ __half Bs[2][64][40];

    const __half* A    = g_xh;
    const __half* Bw   = blockIdx.z ? g_uh : g_wh;
    const float*  bias = blockIdx.z ? Ub : Wb;
    __half*       out  = blockIdx.z ? g_k : g_q;

    const int bn = blockIdx.x * 64;
    const int bm = blockIdx.y * 128;
    const int tid = threadIdx.x, warp = tid >> 5, lane = tid & 31;
    const int wm = warp >> 1, wn = warp & 1;
    const int gq = lane >> 2, tq = lane & 3;

    const int ar0 = tid >> 2, aq = tid & 3;
    const int br  = tid >> 2, bq = tid & 3;

    float acc[2][4][4] = {};

    cp16(&As[0][ar0][aq * 8],      &A[(bm + ar0) * DD + aq * 8]);
    cp16(&As[0][ar0 + 64][aq * 8], &A[(bm + ar0 + 64) * DD + aq * 8]);
    cp16(&Bs[0][br][bq * 8],       &Bw[(bn + br) * DD + bq * 8]);
    CP_COMMIT();

    #pragma unroll
    for (int it = 0; it < 8; it++) {
        CP_WAIT0();
        __syncthreads();
        if (it < 7) {
            int nk = (it + 1) * 32, s = (it + 1) & 1;
            cp16(&As[s][ar0][aq * 8],      &A[(bm + ar0) * DD + nk + aq * 8]);
            cp16(&As[s][ar0 + 64][aq * 8], &A[(bm + ar0 + 64) * DD + nk + aq * 8]);
            cp16(&Bs[s][br][bq * 8],       &Bw[(bn + br) * DD + nk + bq * 8]);
            CP_COMMIT();
        }
        const int cur = it & 1;

        #pragma unroll
        for (int ks = 0; ks < 2; ks++) {
            int kc = ks * 16;
            unsigned a[2][4], bf[2][4];
            #pragma unroll
            for (int tm = 0; tm < 2; tm++) {
                int r = wm * 32 + tm * 16 + (lane & 15);
                int c = kc + 8 * (lane >> 4);
                ldsm_x4(a[tm], &As[cur][r][c]);
            }
            #pragma unroll
            for (int tn = 0; tn < 2; tn++) {
                int r = wn * 32 + tn * 16 + (lane & 7) + 8 * (lane >> 4);
                int c = kc + 8 * ((lane >> 3) & 1);
                ldsm_x4(bf[tn], &Bs[cur][r][c]);
            }
            #pragma unroll
            for (int tm = 0; tm < 2; tm++)
                #pragma unroll
                for (int tn8 = 0; tn8 < 4; tn8++)
                    mma16816(acc[tm][tn8], a[tm],
                             bf[tn8 >> 1][(tn8 & 1) * 2],
                             bf[tn8 >> 1][(tn8 & 1) * 2 + 1]);
        }
    }

    #pragma unroll
    for (int tm = 0; tm < 2; tm++) {
        #pragma unroll
        for (int tn8 = 0; tn8 < 4; tn8++) {
            int c = bn + wn * 32 + tn8 * 8 + 2 * tq;
            float2 bv = *(const float2*)&bias[c];
            int r0 = bm + wm * 32 + tm * 16 + gq;
            __half2 h0 = __floats2half2_rn(acc[tm][tn8][0] + bv.x,
                                           acc[tm][tn8][1] + bv.y);
            __half2 h1 = __floats2half2_rn(acc[tm][tn8][2] + bv.x,
                                           acc[tm][tn8][3] + bv.y);
            *(__half2*)&out[r0 * DD + c] = h0;
            *(__half2*)&out[(r0 + 8) * DD + c] = h1;
        }
    }
}

// ---------------- kernel 2: additive-attention scores (R11 body, occ 3) -----
// wei[b,q,k] = sum_d Va[d] * tanh(q[b,q,d] + k[b,k,d])
// HFMA2 fp16 accumulation (4 accumulators x 4 products), single fp32
// conversion per qi. Va pre-packed to half2. Occupancy raised 2 -> 3
// blocks/SM (6 warps/SMSP) to test/exploit the latency-bound hypothesis.
#define KT 32
#define QB 64
#define QSTAGE 32

__global__ __launch_bounds__(256, 3) void score_kernel(const float* __restrict__ Va)
{
    __shared__ __align__(16) unsigned q_sh[QSTAGE][320];  // 40 KB

    const int tid  = threadIdx.x;
    const int w    = tid >> 5;
    const int lane = tid & 31;
    const int dg   = lane >> 2;
    const int kis  = lane & 3;

    const int b     = blockIdx.z;
    const int k0    = blockIdx.x * KT;
    const int qbase = blockIdx.y * QB;
    const int krow  = k0 + w * 4 + kis;

    unsigned kreg[16];
    {
        const uint4* kp = reinterpret_cast<const uint4*>(
            g_k + ((b * NN + krow) << 8) + dg * 32);
        #pragma unroll
        for (int j = 0; j < 4; j++) {
            uint4 t = kp[j];
            kreg[4*j+0] = t.x; kreg[4*j+1] = t.y;
            kreg[4*j+2] = t.z; kreg[4*j+3] = t.w;
        }
    }
    unsigned vh[16];
    {
        const float4* vp = reinterpret_cast<const float4*>(Va + dg * 32);
        #pragma unroll
        for (int j = 0; j < 8; j++) {
            float4 v = vp[j];
            __half2 a = __floats2half2_rn(v.x, v.y);
            __half2 c = __floats2half2_rn(v.z, v.w);
            vh[2*j]   = *reinterpret_cast<unsigned*>(&a);
            vh[2*j+1] = *reinterpret_cast<unsigned*>(&c);
        }
    }

    for (int qc = 0; qc < QB; qc += QSTAGE) {
        __syncthreads();
        const uint4* gq4 = reinterpret_cast<const uint4*>(
            g_q + ((b * NN + qbase + qc) << 8));
        #pragma unroll
        for (int l = 0; l < 4; l++) {
            int idx = tid + 256 * l;
            int r  = idx >> 5;
            int p4 = idx & 31;
            uint4 v = gq4[(r << 5) + p4];
            *reinterpret_cast<uint4*>(&q_sh[r][(p4 >> 2) * 40 + (p4 & 3) * 4]) = v;
        }
        __syncthreads();

        #pragma unroll 2
        for (int qi = 0; qi < QSTAGE; qi++) {
            const uint4* q4 = reinterpret_cast<const uint4*>(&q_sh[qi][dg * 40]);
            unsigned hacc[4] = {0u, 0u, 0u, 0u};
            #pragma unroll
            for (int j = 0; j < 4; j++) {
                uint4 qv = q4[j];
                unsigned qh[4] = {qv.x, qv.y, qv.z, qv.w};
                #pragma unroll
                for (int u = 0; u < 4; u++) {
                    int i = 4 * j + u;
                    unsigned t = tanh_h2(hadd2_u(qh[u], kreg[i]));
                    hacc[u] = hfma2_u(t, vh[i], hacc[u]);
                }
            }
            float2 f0 = __half22float2(*reinterpret_cast<__half2*>(&hacc[0]));
            float2 f1 = __half22float2(*reinterpret_cast<__half2*>(&hacc[1]));
            float2 f2 = __half22float2(*reinterpret_cast<__half2*>(&hacc[2]));
            float2 f3 = __half22float2(*reinterpret_cast<__half2*>(&hacc[3]));
            float partial = ((f0.x + f0.y) + (f1.x + f1.y))
                          + ((f2.x + f2.y) + (f3.x + f3.y));
            partial += __shfl_xor_sync(0xffffffffu, partial, 16);
            partial += __shfl_xor_sync(0xffffffffu, partial, 8);
            partial += __shfl_xor_sync(0xffffffffu, partial, 4);
            if (dg == 0) {
                g_wei[((b * NN + qbase + qc + qi) << 9) + krow] = partial;
            }
        }
    }
}

// ---------------- kernel 3: masked softmax -> fp16 weights -------------------
__global__ __launch_bounds__(128) void softmax_kernel(const int* __restrict__ mask)
{
    const int row = blockIdx.x;
    const float* wrow = g_wei + row * NN;
    const int* mrow = mask + row * NN;
    const int t = threadIdx.x;
    __shared__ float red[4];

    float4 v = reinterpret_cast<const float4*>(wrow)[t];
    int4   m = reinterpret_cast<const int4*>(mrow)[t];
    if (m.x == 0) v.x = -1e30f;
    if (m.y == 0) v.y = -1e30f;
    if (m.z == 0) v.z = -1e30f;
    if (m.w == 0) v.w = -1e30f;

    float mx = fmaxf(fmaxf(v.x, v.y), fmaxf(v.z, v.w));
    #pragma unroll
    for (int s = 16; s > 0; s >>= 1) mx = fmaxf(mx, __shfl_xor_sync(0xffffffffu, mx, s));
    if ((t & 31) == 0) red[t >> 5] = mx;
    __syncthreads();
    mx = fmaxf(fmaxf(red[0], red[1]), fmaxf(red[2], red[3]));
    __syncthreads();

    v.x = __expf(v.x - mx); v.y = __expf(v.y - mx);
    v.z = __expf(v.z - mx); v.w = __expf(v.w - mx);
    float sum = (v.x + v.y) + (v.z + v.w);
    #pragma unroll
    for (int s = 16; s > 0; s >>= 1) sum += __shfl_xor_sync(0xffffffffu, sum, s);
    if ((t & 31) == 0) red[t >> 5] = sum;
    __syncthreads();
    sum = (red[0] + red[1]) + (red[2] + red[3]);
    float inv = 1.0f / sum;

    __half2 h01 = __floats2half2_rn(v.x * inv, v.y * inv);
    __half2 h23 = __floats2half2_rn(v.z * inv, v.w * inv);
    uint2 o;
    o.x = *reinterpret_cast<unsigned*>(&h01);
    o.y = *reinterpret_cast<unsigned*>(&h23);
    reinterpret_cast<uint2*>(g_weih + row * NN)[t] = o;
}

// ---------------- kernel 4: out = wei @ X via HMMA, cp.async pipelined -------
__global__ __launch_bounds__(256) void av_mma(float* __restrict__ out)
{
    __shared__ __half As[2][64][40];
    __shared__ __half Bs[2][32][72];

    const int b  = blockIdx.z;
    const int bn = blockIdx.x * 64;
    const int bm = blockIdx.y * 64;
    const __half* A  = g_weih + b * NN * NN;
    const __half* Bx = g_xh + b * NN * DD;

    const int tid = threadIdx.x, warp = tid >> 5, lane = tid & 31;
    const int wm = warp >> 2, wn = warp & 3;
    const int gq = lane >> 2, tq = lane & 3;

    const int ar = tid >> 2, aq = tid & 3;
    const int br = tid >> 3, bq = tid & 7;

    float acc[2][2][4] = {};

    cp16(&As[0][ar][aq * 8], &A[(bm + ar) * NN + aq * 8]);
    cp16(&Bs[0][br][bq * 8], &Bx[br * DD + bn + bq * 8]);
    CP_COMMIT();

    #pragma unroll 1
    for (int it = 0; it < 16; it++) {
        CP_WAIT0();
        __syncthreads();
        if (it < 15) {
            int nk = (it + 1) * 32, s = (it + 1) & 1;
            cp16(&As[s][ar][aq * 8], &A[(bm + ar) * NN + nk + aq * 8]);
            cp16(&Bs[s][br][bq * 8], &Bx[(nk + br) * DD + bn + bq * 8]);
            CP_COMMIT();
        }
        const int cur = it & 1;

        #pragma unroll
        for (int ks = 0; ks < 2; ks++) {
            int kc = ks * 16;
            unsigned a[2][4], bf[4];
            #pragma unroll
            for (int tm = 0; tm < 2; tm++) {
                int r = wm * 32 + tm * 16 + (lane & 15);
                int c = kc + 8 * (lane >> 4);
                ldsm_x4(a[tm], &As[cur][r][c]);
            }
            {
                int kr = kc + (lane & 7) + 8 * ((lane >> 3) & 1);
                int nc = wn * 16 + 8 * (lane >> 4);
                ldsm_x4_trans(bf, &Bs[cur][kr][nc]);
            }
            #pragma unroll
            for (int tm = 0; tm < 2; tm++)
                #pragma unroll
                for (int tn8 = 0; tn8 < 2; tn8++)
                    mma16816(acc[tm][tn8], a[tm], bf[tn8 * 2], bf[tn8 * 2 + 1]);
        }
    }

    #pragma unroll
    for (int tm = 0; tm < 2; tm++) {
        #pragma unroll
        for (int tn8 = 0; tn8 < 2; tn8++) {
            int c  = bn + wn * 16 + tn8 * 8 + 2 * tq;
            int r0 = bm + wm * 32 + tm * 16 + gq;
            *(float2*)&out[(b * NN + r0) * DD + c] =
                make_float2(acc[tm][tn8][0], acc[tm][tn8][1]);
            *(float2*)&out[(b * NN + r0 + 8) * DD + c] =
                make_float2(acc[tm][tn8][2], acc[tm][tn8][3]);
        }
    }
}

// ---------------- launcher ---------------------------------------------------
extern "C" void kernel_launch(void* const* d_in, const int* in_sizes, int n_in,
                              void* d_out, int out_size)
{
    const float* X    = (const float*)d_in[0];  // [4,512,256]
    const int*   mask = (const int*)  d_in[1];  // [4,512,512]
    const float* Wa_w = (const float*)d_in[2];  // [256,256]
    const float* Wa_b = (const float*)d_in[3];  // [256]
    const float* Ua_w = (const float*)d_in[4];  // [256,256]
    const float* Ua_b = (const float*)d_in[5];  // [256]
    const float* Va_w = (const float*)d_in[6];  // [1,256]
    // d_in[7] = Va_b : softmax-invariant constant -> unused

    (void)in_sizes; (void)n_in; (void)out_size;

    conv_kernel<<<640, 256>>>((const float4*)X, (const float4*)Wa_w,
                              (const float4*)Ua_w);

    dim3 pgrid(DD / 64, (BB * NN) / 128, 2);    // 128 blocks
    proj_mma<<<pgrid, 256>>>(Wa_b, Ua_b);

    dim3 sgrid(NN / KT, NN / QB, BB);           // 512 blocks
    score_kernel<<<sgrid, 256>>>(Va_w);

    softmax_kernel<<<BB * NN, 128>>>(mask);

    dim3 agrid(DD / 64, NN / 64, BB);           // 128 blocks
    av_mma<<<agrid, 256>>>((float*)d_out);
}